// round 7
// baseline (speedup 1.0000x reference)
#include <cuda_runtime.h>
#include <math.h>

#define BATCH   32768
#define NB      16
#define K       32
#define NSTATE  (NB*K)       // 256
#define IN_DIM  64
#define DT_C    0.05f
#define TAU_EPS 1e-6f
#define TPB     128          // step kernel block size (2 batch elems / thread)
#define PTPB    256          // precompute block size
#define HALF_B  (BATCH/2)    // 16384

typedef unsigned long long u64t;

// Scratch (allocation-free rule: __device__ globals)
__device__ float g_buf0[BATCH*NSTATE];
__device__ float g_buf1[BATCH*NSTATE];
__device__ float g_T0[BATCH*K];   // E_l[0] @ net0  (constant across steps)
__device__ float g_a0[BATCH*K];   // |net0|         (constant across steps)

// E_l (all 16 blocks) in constant memory as packed f32x2 pairs. 64KB.
__constant__ __align__(16) u64t c_El[NB*K*K/2];

__device__ __forceinline__ float fast_tanh(float x) {
    float r;
    asm("tanh.approx.f32 %0, %1;" : "=f"(r) : "f"(x));
    return r;
}

// ---- packed f32x2 helpers ----
__device__ __forceinline__ u64t pack2(float lo, float hi) {
    u64t d; asm("mov.b64 %0, {%1, %2};" : "=l"(d) : "f"(lo), "f"(hi)); return d;
}
__device__ __forceinline__ void unpack2(float& lo, float& hi, u64t v) {
    asm("mov.b64 {%0, %1}, %2;" : "=f"(lo), "=f"(hi) : "l"(v));
}
__device__ __forceinline__ u64t fma2(u64t a, u64t b, u64t c) {
    u64t d; asm("fma.rn.f32x2 %0, %1, %2, %3;" : "=l"(d) : "l"(a), "l"(b), "l"(c)); return d;
}
__device__ __forceinline__ u64t add2(u64t a, u64t b) {
    u64t d; asm("add.rn.f32x2 %0, %1, %2;" : "=l"(d) : "l"(a), "l"(b)); return d;
}

// one smem weight row (8x LDS.128) -> TWO dots (elem0, elem1)
__device__ __forceinline__ void dot2s(const float* __restrict__ wrow,
                                      const u64t* v0, const u64t* v1,
                                      float bias, float& r0, float& r1) {
    u64t a00 = pack2(bias, 0.f), a01 = 0ULL;
    u64t a10 = pack2(bias, 0.f), a11 = 0ULL;
    const ulonglong2* w2 = reinterpret_cast<const ulonglong2*>(wrow);
#pragma unroll
    for (int i = 0; i < 8; ++i) {
        ulonglong2 w = w2[i];
        a00 = fma2(w.x, v0[2*i+0], a00); a01 = fma2(w.y, v0[2*i+1], a01);
        a10 = fma2(w.x, v1[2*i+0], a10); a11 = fma2(w.y, v1[2*i+1], a11);
    }
    a00 = add2(a00, a01); a10 = add2(a10, a11);
    float l0,h0,l1,h1; unpack2(l0,h0,a00); unpack2(l1,h1,a10);
    r0 = l0 + h0; r1 = l1 + h1;
}

// const row (c_El, LDCU path) . a_e  +  smem row . b_e, for two elems
__device__ __forceinline__ void dotC2(int cbase,
                                      const u64t* a0v, const u64t* a1v,
                                      const float* __restrict__ wrow,
                                      const u64t* b0v, const u64t* b1v,
                                      float& r0, float& r1) {
    u64t a00 = 0ULL, a01 = 0ULL, a10 = 0ULL, a11 = 0ULL;
#pragma unroll
    for (int i = 0; i < 8; ++i) {
        ulonglong2 wc = *reinterpret_cast<const ulonglong2*>(&c_El[cbase + 2*i]);
        a00 = fma2(wc.x, a0v[2*i+0], a00); a01 = fma2(wc.y, a0v[2*i+1], a01);
        a10 = fma2(wc.x, a1v[2*i+0], a10); a11 = fma2(wc.y, a1v[2*i+1], a11);
    }
    const ulonglong2* w2 = reinterpret_cast<const ulonglong2*>(wrow);
#pragma unroll
    for (int i = 0; i < 8; ++i) {
        ulonglong2 w = w2[i];
        a00 = fma2(w.x, b0v[2*i+0], a00); a01 = fma2(w.y, b0v[2*i+1], a01);
        a10 = fma2(w.x, b1v[2*i+0], a10); a11 = fma2(w.y, b1v[2*i+1], a11);
    }
    a00 = add2(a00, a01); a10 = add2(a10, a11);
    float l0,h0,l1,h1; unpack2(l0,h0,a00); unpack2(l1,h1,a10);
    r0 = l0 + h0; r1 = l1 + h1;
}

__device__ __forceinline__ void load_packed(u64t* dst, const float* __restrict__ p) {
    const ulonglong2* p2 = reinterpret_cast<const ulonglong2*>(p);
#pragma unroll
    for (int i = 0; i < 8; ++i) { ulonglong2 t = p2[i]; dst[2*i] = t.x; dst[2*i+1] = t.y; }
}
__device__ __forceinline__ void store_packed(float* __restrict__ p, const u64t* src) {
    ulonglong2* p2 = reinterpret_cast<ulonglong2*>(p);
#pragma unroll
    for (int i = 0; i < 8; ++i) { ulonglong2 t; t.x = src[2*i]; t.y = src[2*i+1]; p2[i] = t; }
}

// packed dot (single elem) for precompute kernel
__device__ __forceinline__ float dot32p(const float* __restrict__ wrow,
                                        const u64t* v, float bias) {
    u64t a0 = pack2(bias, 0.f), a1 = 0ULL;
    const ulonglong2* w2 = reinterpret_cast<const ulonglong2*>(wrow);
#pragma unroll
    for (int i = 0; i < 8; ++i) {
        ulonglong2 w = w2[i];
        a0 = fma2(w.x, v[2*i+0], a0);
        a1 = fma2(w.y, v[2*i+1], a1);
    }
    a0 = add2(a0, a1);
    float lo, hi; unpack2(lo, hi, a0);
    return lo + hi;
}

// ---------------- Kernel A: net0 precompute ----------------
__global__ __launch_bounds__(PTPB) void ltcn_precompute(
    const float* __restrict__ u_t, const float* __restrict__ W_in,
    const float* __restrict__ b_in, const float* __restrict__ E_l)
{
    __shared__ __align__(16) float sWin[K*IN_DIM];
    __shared__ __align__(16) float sEl0[K*K];
    __shared__ float sbin[K];
    int tid = threadIdx.x;
    for (int i = tid; i < K*IN_DIM; i += PTPB) sWin[i] = W_in[i];
    for (int i = tid; i < K*K;     i += PTPB) sEl0[i] = E_l[i];
    if (tid < K) sbin[tid] = b_in[tid];
    __syncthreads();

    int b = blockIdx.x * PTPB + tid;
    if (b >= BATCH) return;

    u64t u[32];
    load_packed(u,      u_t + (size_t)b * IN_DIM);
    load_packed(u + 16, u_t + (size_t)b * IN_DIM + 32);

    float n0s[K];
#pragma unroll 4
    for (int l = 0; l < K; ++l) {
        const float* wr = sWin + l * IN_DIM;
        u64t a0 = pack2(sbin[l], 0.f), a1 = 0ULL;
        const ulonglong2* w2 = reinterpret_cast<const ulonglong2*>(wr);
#pragma unroll
        for (int i = 0; i < 16; ++i) {
            ulonglong2 w = w2[i];
            a0 = fma2(w.x, u[2*i+0], a0);
            a1 = fma2(w.y, u[2*i+1], a1);
        }
        a0 = add2(a0, a1);
        float lo, hi; unpack2(lo, hi, a0);
        n0s[l] = fast_tanh(lo + hi);
    }

    u64t n0[16];
#pragma unroll
    for (int i = 0; i < 16; ++i) n0[i] = pack2(n0s[2*i], n0s[2*i+1]);

    float t0[K], a0v[K];
#pragma unroll 4
    for (int l = 0; l < K; ++l) {
        t0[l]  = dot32p(sEl0 + l*K, n0, 0.f);
        a0v[l] = fabsf(n0s[l]);
    }
    float4* t0p = reinterpret_cast<float4*>(g_T0 + (size_t)b * K);
    float4* a0p = reinterpret_cast<float4*>(g_a0 + (size_t)b * K);
#pragma unroll
    for (int i = 0; i < 8; ++i) {
        t0p[i] = make_float4(t0[4*i],  t0[4*i+1],  t0[4*i+2],  t0[4*i+3]);
        a0p[i] = make_float4(a0v[4*i], a0v[4*i+1], a0v[4*i+2], a0v[4*i+3]);
    }
}

// ---------------- Step kernel: 2 batch elements per thread ----------------
__global__ __launch_bounds__(TPB, 2) void ltcn_step(
    const float* __restrict__ src, float* __restrict__ dst,
    const float* __restrict__ W_fwd, const float* __restrict__ b_fwd,
    const float* __restrict__ W_rec, const float* __restrict__ b_rec,
    const float* __restrict__ E_lr,
    const float* __restrict__ tau_raw, const int* __restrict__ n_steps, int s)
{
    __shared__ __align__(16) float sWf[K*K];
    __shared__ __align__(16) float sWr[K*K];
    __shared__ __align__(16) float sElr[K*K];
    __shared__ float sbf[K], sbr[K], sit[K];

    int tid = threadIdx.x;
    int j = blockIdx.y;

    for (int i = tid; i < K*K; i += TPB) {
        sWr[i]  = W_rec[j*K*K + i];
        sElr[i] = E_lr [j*K*K + i];
        if (j > 0) sWf[i] = W_fwd[(j-1)*K*K + i];
    }
    if (tid < K) {
        sbr[tid] = b_rec[j*K + tid];
        sbf[tid] = (j > 0) ? b_fwd[(j-1)*K + tid] : 0.f;
        float t  = tau_raw[j*K + tid];
        float sp = (t > 20.f) ? t : log1pf(expf(t));   // softplus
        sit[tid] = 1.0f / (sp + TAU_EPS);
    }
    __syncthreads();

    size_t b0 = (size_t)blockIdx.x * TPB + tid;   // element 0
    size_t b1 = b0 + HALF_B;                      // element 1
    const float* yin0  = src + b0 * NSTATE + (size_t)j * K;
    const float* yin1  = src + b1 * NSTATE + (size_t)j * K;
    float*       yout0 = dst + b0 * NSTATE + (size_t)j * K;
    float*       yout1 = dst + b1 * NSTATE + (size_t)j * K;

    if (s >= *n_steps) {   // passthrough beyond requested steps
        u64t t0[16], t1[16];
        load_packed(t0, yin0); load_packed(t1, yin1);
        store_packed(yout0, t0); store_packed(yout1, t1);
        return;
    }

    u64t y0[16], y1[16];
    load_packed(y0, yin0);
    load_packed(y1, yin1);

    // net_rec = tanh(W_rec[j] @ y + b_rec[j]) for both elems
    u64t nr0[16], nr1[16];
#pragma unroll
    for (int i = 0; i < 16; ++i) {
        float a0, a1, c0, c1;
        dot2s(sWr + (2*i+0)*K, y0, y1, sbr[2*i+0], a0, a1);
        dot2s(sWr + (2*i+1)*K, y0, y1, sbr[2*i+1], c0, c1);
        nr0[i] = pack2(fast_tanh(a0), fast_tanh(c0));
        nr1[i] = pack2(fast_tanh(a1), fast_tanh(c1));
    }

    if (j == 0) {
        u64t t0p0[16], a0p0[16], t0p1[16], a0p1[16];
        load_packed(t0p0, g_T0 + b0 * K); load_packed(a0p0, g_a0 + b0 * K);
        load_packed(t0p1, g_T0 + b1 * K); load_packed(a0p1, g_a0 + b1 * K);
#pragma unroll
        for (int i = 0; i < 16; ++i) {
            float o0lo, o1lo, o0hi, o1hi;
            dot2s(sElr + (2*i+0)*K, nr0, nr1, 0.f, o0lo, o1lo);
            dot2s(sElr + (2*i+1)*K, nr0, nr1, 0.f, o0hi, o1hi);
            float t0lo,t0hi, a0lo,a0hi, nlo,nhi, ylo,yhi;

            unpack2(t0lo,t0hi,t0p0[i]); unpack2(a0lo,a0hi,a0p0[i]);
            unpack2(nlo,nhi,nr0[i]);    unpack2(ylo,yhi,y0[i]);
            ylo = fmaf(DT_C, (o0lo+t0lo) - ylo*(sit[2*i+0]+a0lo+fabsf(nlo)), ylo);
            yhi = fmaf(DT_C, (o0hi+t0hi) - yhi*(sit[2*i+1]+a0hi+fabsf(nhi)), yhi);
            y0[i] = pack2(ylo, yhi);

            unpack2(t0lo,t0hi,t0p1[i]); unpack2(a0lo,a0hi,a0p1[i]);
            unpack2(nlo,nhi,nr1[i]);    unpack2(ylo,yhi,y1[i]);
            ylo = fmaf(DT_C, (o1lo+t0lo) - ylo*(sit[2*i+0]+a0lo+fabsf(nlo)), ylo);
            yhi = fmaf(DT_C, (o1hi+t0hi) - yhi*(sit[2*i+1]+a0hi+fabsf(nhi)), yhi);
            y1[i] = pack2(ylo, yhi);
        }
    } else {
        // net_out = tanh(W_fwd[j-1] @ y_{j-1} + b) from step-start snapshot
        u64t no0[16], no1[16];
        {
            u64t yp0[16], yp1[16];
            load_packed(yp0, src + b0 * NSTATE + (size_t)(j-1) * K);
            load_packed(yp1, src + b1 * NSTATE + (size_t)(j-1) * K);
#pragma unroll
            for (int i = 0; i < 16; ++i) {
                float a0, a1, c0, c1;
                dot2s(sWf + (2*i+0)*K, yp0, yp1, sbf[2*i+0], a0, a1);
                dot2s(sWf + (2*i+1)*K, yp0, yp1, sbf[2*i+1], c0, c1);
                no0[i] = pack2(fast_tanh(a0), fast_tanh(c0));
                no1[i] = pack2(fast_tanh(a1), fast_tanh(c1));
            }
        }
        const int elbase = j * (K*K/2);
#pragma unroll
        for (int i = 0; i < 16; ++i) {
            float o0lo, o1lo, o0hi, o1hi;
            dotC2(elbase + (2*i+0)*(K/2), no0, no1, sElr + (2*i+0)*K, nr0, nr1, o0lo, o1lo);
            dotC2(elbase + (2*i+1)*(K/2), no0, no1, sElr + (2*i+1)*K, nr0, nr1, o0hi, o1hi);

            float nolo,nohi, nrlo,nrhi, ylo,yhi;
            unpack2(nolo,nohi,no0[i]); unpack2(nrlo,nrhi,nr0[i]); unpack2(ylo,yhi,y0[i]);
            ylo = fmaf(DT_C, o0lo - ylo*(sit[2*i+0]+fabsf(nolo)+fabsf(nrlo)), ylo);
            yhi = fmaf(DT_C, o0hi - yhi*(sit[2*i+1]+fabsf(nohi)+fabsf(nrhi)), yhi);
            y0[i] = pack2(ylo, yhi);

            unpack2(nolo,nohi,no1[i]); unpack2(nrlo,nrhi,nr1[i]); unpack2(ylo,yhi,y1[i]);
            ylo = fmaf(DT_C, o1lo - ylo*(sit[2*i+0]+fabsf(nolo)+fabsf(nrlo)), ylo);
            yhi = fmaf(DT_C, o1hi - yhi*(sit[2*i+1]+fabsf(nohi)+fabsf(nrhi)), yhi);
            y1[i] = pack2(ylo, yhi);
        }
    }

    store_packed(yout0, y0);
    store_packed(yout1, y1);
}

extern "C" void kernel_launch(void* const* d_in, const int* in_sizes, int n_in,
                              void* d_out, int out_size)
{
    const float* y     = (const float*)d_in[0];
    const float* u_t   = (const float*)d_in[1];
    const float* W_in  = (const float*)d_in[2];
    const float* b_in  = (const float*)d_in[3];
    const float* W_fwd = (const float*)d_in[4];
    const float* b_fwd = (const float*)d_in[5];
    const float* W_rec = (const float*)d_in[6];
    const float* b_rec = (const float*)d_in[7];
    const float* E_l   = (const float*)d_in[8];
    const float* E_lr  = (const float*)d_in[9];
    const float* tau   = (const float*)d_in[10];
    const int*   nst   = (const int*)d_in[11];
    float* out = (float*)d_out;

    float *buf0, *buf1;
    cudaGetSymbolAddress((void**)&buf0, g_buf0);
    cudaGetSymbolAddress((void**)&buf1, g_buf1);

    // E_l -> constant memory (same bytes; viewed as packed f32x2 pairs)
    cudaMemcpyToSymbolAsync(c_El, E_l, NB*K*K*sizeof(float), 0,
                            cudaMemcpyDeviceToDevice, 0);

    ltcn_precompute<<<BATCH/PTPB, PTPB>>>(u_t, W_in, b_in, E_l);

    dim3 grid(BATCH/(TPB*2), NB);
    for (int s = 0; s < 8; ++s) {
        const float* srcp = (s == 0) ? y   : ((s & 1) ? buf0 : buf1);
        float*       dstp = (s == 7) ? out : ((s & 1) ? buf1 : buf0);
        ltcn_step<<<grid, TPB>>>(srcp, dstp, W_fwd, b_fwd, W_rec, b_rec,
                                 E_lr, tau, nst, s);
    }
}

// round 10
// speedup vs baseline: 1.8868x; 1.8868x over previous
#include <cuda_runtime.h>
#include <cstdint>
#include <math.h>

#define BATCH   32768
#define NBLK    16
#define KD      32
#define NSTATE  (NBLK*KD)    // 512
#define INDIM   64
#define DT_C    0.05f
#define TAU_EPS 1e-6f
#define MTILE   128
#define TPB     128
#define PTPB    256

// smem float offsets (row stride 36 floats => conflict-free fragment loads)
#define ST      36
#define SY      0                 // y_j tile      128x36
#define SYP     (SY   + 128*ST)   // y_{j-1} tile  128x36
#define SAA     (SYP  + 128*ST)   // act A (net_out) 128x36
#define SAR     (SAA  + 128*ST)   // act R (net_rec) 128x36
#define SWF     (SAR  + 128*ST)   // W_fwd  32x36
#define SWR     (SWF  + 32*ST)
#define SEL     (SWR  + 32*ST)
#define SELR    (SEL  + 32*ST)
#define SBF     (SELR + 32*ST)
#define SBR     (SBF  + 32)
#define SSIT    (SBR  + 32)
#define SM_FLOATS (SSIT + 32)
#define SMEM_BYTES (SM_FLOATS*4)

__device__ float g_buf0[BATCH*NSTATE];
__device__ float g_buf1[BATCH*NSTATE];
__device__ float g_net0[BATCH*KD];   // tanh(u@W_in^T + b_in), constant across steps

__device__ __forceinline__ float fast_tanh(float x) {
    float r; asm("tanh.approx.f32 %0, %1;" : "=f"(r) : "f"(x)); return r;
}
__device__ __forceinline__ float to_tf32f(float f) {
    uint32_t r; asm("cvt.rna.tf32.f32 %0, %1;" : "=r"(r) : "f"(f));
    return __uint_as_float(r);
}
__device__ __forceinline__ void mma8(float c[4], float a0, float a1, float a2,
                                     float a3, float b0, float b1) {
    asm volatile(
        "mma.sync.aligned.m16n8k8.row.col.f32.tf32.tf32.f32 "
        "{%0,%1,%2,%3}, {%4,%5,%6,%7}, {%8,%9}, {%0,%1,%2,%3};"
        : "+f"(c[0]), "+f"(c[1]), "+f"(c[2]), "+f"(c[3])
        : "r"(__float_as_uint(a0)), "r"(__float_as_uint(a1)),
          "r"(__float_as_uint(a2)), "r"(__float_as_uint(a3)),
          "r"(__float_as_uint(b0)), "r"(__float_as_uint(b1)));
}

// C[2][4][4] += A(rows rowbase..rowbase+31 of sA) @ W^T   (W: 32x32, stride ST)
__device__ __forceinline__ void gemm32(const float* __restrict__ sA, int rowbase,
                                       const float* __restrict__ sW,
                                       float C[2][4][4], int g, int tig) {
    float B[4][4][2];
#pragma unroll
    for (int nt = 0; nt < 4; ++nt)
#pragma unroll
        for (int ks = 0; ks < 4; ++ks) {
            const float* wr = sW + (nt*8 + g)*ST + ks*8;
            B[nt][ks][0] = wr[tig];
            B[nt][ks][1] = wr[tig + 4];
        }
#pragma unroll
    for (int t = 0; t < 2; ++t) {
        int rb = rowbase + 16*t;
#pragma unroll
        for (int ks = 0; ks < 4; ++ks) {
            const float* a  = sA + (rb + g)*ST + ks*8;
            const float* a8 = sA + (rb + g + 8)*ST + ks*8;
            float a0 = a[tig], a1 = a8[tig], a2 = a[tig+4], a3 = a8[tig+4];
#pragma unroll
            for (int nt = 0; nt < 4; ++nt)
                mma8(C[t][nt], a0, a1, a2, a3, B[nt][ks][0], B[nt][ks][1]);
        }
    }
}

// ---------------- Kernel A: net0 precompute ----------------
__global__ __launch_bounds__(PTPB) void ltcn_precompute(
    const float* __restrict__ u_t, const float* __restrict__ W_in,
    const float* __restrict__ b_in)
{
    __shared__ __align__(16) float sWin[KD*INDIM];
    __shared__ float sbin[KD];
    int tid = threadIdx.x;
    for (int i = tid; i < KD*INDIM; i += PTPB) sWin[i] = W_in[i];
    if (tid < KD) sbin[tid] = b_in[tid];
    __syncthreads();

    int b = blockIdx.x * PTPB + tid;
    if (b >= BATCH) return;

    float u[INDIM];
    const float4* up = reinterpret_cast<const float4*>(u_t + (size_t)b * INDIM);
#pragma unroll
    for (int i = 0; i < INDIM/4; ++i) {
        float4 t = up[i];
        u[4*i+0]=t.x; u[4*i+1]=t.y; u[4*i+2]=t.z; u[4*i+3]=t.w;
    }
    float n0[KD];
#pragma unroll 4
    for (int l = 0; l < KD; ++l) {
        float acc = sbin[l];
        const float4* wr = reinterpret_cast<const float4*>(sWin + l*INDIM);
#pragma unroll
        for (int i = 0; i < INDIM/4; ++i) {
            float4 w = wr[i];
            acc = fmaf(w.x, u[4*i+0], acc);
            acc = fmaf(w.y, u[4*i+1], acc);
            acc = fmaf(w.z, u[4*i+2], acc);
            acc = fmaf(w.w, u[4*i+3], acc);
        }
        n0[l] = fast_tanh(acc);
    }
    float4* op = reinterpret_cast<float4*>(g_net0 + (size_t)b * KD);
#pragma unroll
    for (int i = 0; i < 8; ++i)
        op[i] = make_float4(n0[4*i], n0[4*i+1], n0[4*i+2], n0[4*i+3]);
}

// ---------------- Step kernel: warp mma.sync tf32 ----------------
__global__ __launch_bounds__(TPB, 2) void ltcn_step_mma(
    const float* __restrict__ src, float* __restrict__ dst,
    const float* __restrict__ W_fwd, const float* __restrict__ b_fwd,
    const float* __restrict__ W_rec, const float* __restrict__ b_rec,
    const float* __restrict__ E_l,   const float* __restrict__ E_lr,
    const float* __restrict__ tau_raw, const int* __restrict__ n_steps, int s)
{
    extern __shared__ __align__(16) float smf[];
    const int tid  = threadIdx.x;
    const int wid  = tid >> 5;
    const int lane = tid & 31;
    const int g    = lane >> 2;
    const int tig  = lane & 3;
    const int j    = blockIdx.y;
    const int gRow = blockIdx.x * MTILE;

    const float* ysl = src + (size_t)(gRow)*NSTATE + (size_t)j*KD;  // [row][NSTATE]
    float*       odl = dst + (size_t)(gRow)*NSTATE + (size_t)j*KD;

    if (s >= *n_steps) {   // passthrough
        const float4* in4 = reinterpret_cast<const float4*>(ysl + (size_t)tid*NSTATE);
        float4*       o4  = reinterpret_cast<float4*>(odl + (size_t)tid*NSTATE);
#pragma unroll
        for (int i = 0; i < 8; ++i) o4[i] = in4[i];
        return;
    }

    // ---- stage tiles (thread = row) ----
    {
        const float4* yr = reinterpret_cast<const float4*>(ysl + (size_t)tid*NSTATE);
#pragma unroll
        for (int i = 0; i < 8; ++i) {
            float4 v = yr[i];
            *reinterpret_cast<float4*>(smf + SY + tid*ST + 4*i) =
                make_float4(to_tf32f(v.x), to_tf32f(v.y), to_tf32f(v.z), to_tf32f(v.w));
        }
        if (j > 0) {
            const float4* ypr = reinterpret_cast<const float4*>(
                src + (size_t)(gRow + tid)*NSTATE + (size_t)(j-1)*KD);
#pragma unroll
            for (int i = 0; i < 8; ++i) {
                float4 v = ypr[i];
                *reinterpret_cast<float4*>(smf + SYP + tid*ST + 4*i) =
                    make_float4(to_tf32f(v.x), to_tf32f(v.y), to_tf32f(v.z), to_tf32f(v.w));
            }
        } else {
            const float4* n0r = reinterpret_cast<const float4*>(
                g_net0 + (size_t)(gRow + tid)*KD);
#pragma unroll
            for (int i = 0; i < 8; ++i) {
                float4 v = n0r[i];
                *reinterpret_cast<float4*>(smf + SAA + tid*ST + 4*i) =
                    make_float4(to_tf32f(v.x), to_tf32f(v.y), to_tf32f(v.z), to_tf32f(v.w));
            }
        }
    }
    // weights: 256 float4 chunks per matrix, 2 per thread
#pragma unroll
    for (int rep = 0; rep < 2; ++rep) {
        int idx = tid + rep*TPB;          // 0..255
        int l = idx >> 3, c4 = idx & 7;
        int so = l*ST + c4*4;
        float4 w;
        w = reinterpret_cast<const float4*>(W_rec + j*KD*KD)[idx];
        *reinterpret_cast<float4*>(smf + SWR + so) =
            make_float4(to_tf32f(w.x), to_tf32f(w.y), to_tf32f(w.z), to_tf32f(w.w));
        w = reinterpret_cast<const float4*>(E_l + j*KD*KD)[idx];
        *reinterpret_cast<float4*>(smf + SEL + so) =
            make_float4(to_tf32f(w.x), to_tf32f(w.y), to_tf32f(w.z), to_tf32f(w.w));
        w = reinterpret_cast<const float4*>(E_lr + j*KD*KD)[idx];
        *reinterpret_cast<float4*>(smf + SELR + so) =
            make_float4(to_tf32f(w.x), to_tf32f(w.y), to_tf32f(w.z), to_tf32f(w.w));
        if (j > 0) {
            w = reinterpret_cast<const float4*>(W_fwd + (j-1)*KD*KD)[idx];
            *reinterpret_cast<float4*>(smf + SWF + so) =
                make_float4(to_tf32f(w.x), to_tf32f(w.y), to_tf32f(w.z), to_tf32f(w.w));
        }
    }
    if (tid < KD) {
        smf[SBR + tid] = b_rec[j*KD + tid];
        if (j > 0) smf[SBF + tid] = b_fwd[(j-1)*KD + tid];
        float t  = tau_raw[j*KD + tid];
        float sp = (t > 20.f) ? t : log1pf(expf(t));
        smf[SSIT + tid] = 1.0f / (sp + TAU_EPS);
    }
    __syncthreads();

    const int rowbase = wid * 32;
    float rabs[2][4][4], aabs[2][4][4];

    // ---- GEMM R + epilogue (tanh, |.|, store actR tf32) ----
    {
        float C[2][4][4];
#pragma unroll
        for (int t=0;t<2;++t)
#pragma unroll
            for (int nt=0;nt<4;++nt)
#pragma unroll
                for (int q=0;q<4;++q) C[t][nt][q] = 0.f;
        gemm32(smf + SY, rowbase, smf + SWR, C, g, tig);
#pragma unroll
        for (int t=0;t<2;++t)
#pragma unroll
            for (int nt=0;nt<4;++nt) {
                int col = nt*8 + 2*tig;
                float b0 = smf[SBR+col], b1 = smf[SBR+col+1];
#pragma unroll
                for (int h=0;h<2;++h) {
                    int r = rowbase + 16*t + g + 8*h;
                    float a0 = fast_tanh(C[t][nt][2*h+0] + b0);
                    float a1 = fast_tanh(C[t][nt][2*h+1] + b1);
                    rabs[t][nt][2*h+0] = fabsf(a0);
                    rabs[t][nt][2*h+1] = fabsf(a1);
                    *reinterpret_cast<float2*>(smf + SAR + r*ST + col) =
                        make_float2(to_tf32f(a0), to_tf32f(a1));
                }
            }
    }

    // ---- GEMM P + epilogue (j>0) ----
    if (j > 0) {
        float C[2][4][4];
#pragma unroll
        for (int t=0;t<2;++t)
#pragma unroll
            for (int nt=0;nt<4;++nt)
#pragma unroll
                for (int q=0;q<4;++q) C[t][nt][q] = 0.f;
        gemm32(smf + SYP, rowbase, smf + SWF, C, g, tig);
#pragma unroll
        for (int t=0;t<2;++t)
#pragma unroll
            for (int nt=0;nt<4;++nt) {
                int col = nt*8 + 2*tig;
                float b0 = smf[SBF+col], b1 = smf[SBF+col+1];
#pragma unroll
                for (int h=0;h<2;++h) {
                    int r = rowbase + 16*t + g + 8*h;
                    float a0 = fast_tanh(C[t][nt][2*h+0] + b0);
                    float a1 = fast_tanh(C[t][nt][2*h+1] + b1);
                    aabs[t][nt][2*h+0] = fabsf(a0);
                    aabs[t][nt][2*h+1] = fabsf(a1);
                    *reinterpret_cast<float2*>(smf + SAA + r*ST + col) =
                        make_float2(to_tf32f(a0), to_tf32f(a1));
                }
            }
    } else {
        // |net0| in C layout straight from gmem
#pragma unroll
        for (int t=0;t<2;++t)
#pragma unroll
            for (int nt=0;nt<4;++nt) {
                int col = nt*8 + 2*tig;
#pragma unroll
                for (int h=0;h<2;++h) {
                    int r = rowbase + 16*t + g + 8*h;
                    float2 v = *reinterpret_cast<const float2*>(
                        g_net0 + (size_t)(gRow + r)*KD + col);
                    aabs[t][nt][2*h+0] = fabsf(v.x);
                    aabs[t][nt][2*h+1] = fabsf(v.y);
                }
            }
    }
    __syncwarp();   // actA/actR rows are warp-local; warp-level visibility suffices

    // ---- GEMM O = actA @ El^T + actR @ Elr^T ----
    float CO[2][4][4];
#pragma unroll
    for (int t=0;t<2;++t)
#pragma unroll
        for (int nt=0;nt<4;++nt)
#pragma unroll
            for (int q=0;q<4;++q) CO[t][nt][q] = 0.f;
    gemm32(smf + SAA, rowbase, smf + SEL,  CO, g, tig);
    gemm32(smf + SAR, rowbase, smf + SELR, CO, g, tig);

    // ---- final integrate + store (C layout, fp32 y reloaded from gmem) ----
#pragma unroll
    for (int t=0;t<2;++t)
#pragma unroll
        for (int nt=0;nt<4;++nt) {
            int col = nt*8 + 2*tig;
            float s0 = smf[SSIT+col], s1 = smf[SSIT+col+1];
#pragma unroll
            for (int h=0;h<2;++h) {
                int r = rowbase + 16*t + g + 8*h;
                float2 yv = *reinterpret_cast<const float2*>(
                    ysl + (size_t)r*NSTATE + col);
                float d0 = s0 + aabs[t][nt][2*h+0] + rabs[t][nt][2*h+0];
                float d1 = s1 + aabs[t][nt][2*h+1] + rabs[t][nt][2*h+1];
                float y0 = fmaf(DT_C, CO[t][nt][2*h+0] - yv.x*d0, yv.x);
                float y1 = fmaf(DT_C, CO[t][nt][2*h+1] - yv.y*d1, yv.y);
                *reinterpret_cast<float2*>(odl + (size_t)r*NSTATE + col) =
                    make_float2(y0, y1);
            }
        }
}

extern "C" void kernel_launch(void* const* d_in, const int* in_sizes, int n_in,
                              void* d_out, int out_size)
{
    const float* y     = (const float*)d_in[0];
    const float* u_t   = (const float*)d_in[1];
    const float* W_in  = (const float*)d_in[2];
    const float* b_in  = (const float*)d_in[3];
    const float* W_fwd = (const float*)d_in[4];
    const float* b_fwd = (const float*)d_in[5];
    const float* W_rec = (const float*)d_in[6];
    const float* b_rec = (const float*)d_in[7];
    const float* E_l   = (const float*)d_in[8];
    const float* E_lr  = (const float*)d_in[9];
    const float* tau   = (const float*)d_in[10];
    const int*   nst   = (const int*)d_in[11];
    float* out = (float*)d_out;

    float *buf0, *buf1;
    cudaGetSymbolAddress((void**)&buf0, g_buf0);
    cudaGetSymbolAddress((void**)&buf1, g_buf1);

    cudaFuncSetAttribute(ltcn_step_mma,
                         cudaFuncAttributeMaxDynamicSharedMemorySize, SMEM_BYTES);

    ltcn_precompute<<<BATCH/PTPB, PTPB>>>(u_t, W_in, b_in);

    dim3 grid(BATCH/MTILE, NBLK);
    for (int s = 0; s < 8; ++s) {
        const float* srcp = (s == 0) ? y   : ((s & 1) ? buf0 : buf1);
        float*       dstp = (s == 7) ? out : ((s & 1) ? buf1 : buf0);
        ltcn_step_mma<<<grid, TPB, SMEM_BYTES>>>(srcp, dstp, W_fwd, b_fwd,
                                                 W_rec, b_rec, E_l, E_lr,
                                                 tau, nst, s);
    }
}

// round 11
// speedup vs baseline: 1.8969x; 1.0053x over previous
#include <cuda_runtime.h>
#include <cstdint>
#include <math.h>

#define BATCH   32768
#define NBLK    16
#define KD      32
#define NSTATE  (NBLK*KD)    // 512
#define INDIM   64
#define DT_C    0.05f
#define TAU_EPS 1e-6f
#define MTILE   128
#define TPB     128
#define PTPB    256

// smem float offsets; ST=36 row stride (conflict-free phases)
#define ST      36
#define SBUFA   0                    // y_{j-1}/net0 -> actA (128x36)
#define SBUFB   (SBUFA + 128*ST)     // y_j -> actR          (128x36)
#define SWF     (SBUFB + 128*ST)     // 32x36 each
#define SWR     (SWF  + 32*ST)
#define SEL     (SWR  + 32*ST)
#define SELR    (SEL  + 32*ST)
#define SBF     (SELR + 32*ST)
#define SBR     (SBF + 32)
#define SSIT    (SBR + 32)
#define SM_FLOATS (SSIT + 32)
#define SMEM_BYTES (SM_FLOATS*4)

// K-column permutation: col c -> p(c); A and W tiles both permuted along K
#define PERM(c) ((((c)&3)<<3) + (((c)>>3)<<1) + (((c)>>2)&1))

__device__ float g_buf0[BATCH*NSTATE];
__device__ float g_buf1[BATCH*NSTATE];
__device__ float g_net0[BATCH*KD];

__device__ __forceinline__ float fast_tanh(float x) {
    float r; asm("tanh.approx.f32 %0, %1;" : "=f"(r) : "f"(x)); return r;
}
__device__ __forceinline__ float to_tf32f(float f) {
    uint32_t r; asm("cvt.rna.tf32.f32 %0, %1;" : "=r"(r) : "f"(f));
    return __uint_as_float(r);
}
__device__ __forceinline__ void mma8(float c[4], float a0, float a1, float a2,
                                     float a3, float b0, float b1) {
    asm volatile(
        "mma.sync.aligned.m16n8k8.row.col.f32.tf32.tf32.f32 "
        "{%0,%1,%2,%3}, {%4,%5,%6,%7}, {%8,%9}, {%0,%1,%2,%3};"
        : "+f"(c[0]), "+f"(c[1]), "+f"(c[2]), "+f"(c[3])
        : "r"(__float_as_uint(a0)), "r"(__float_as_uint(a1)),
          "r"(__float_as_uint(a2)), "r"(__float_as_uint(a3)),
          "r"(__float_as_uint(b0)), "r"(__float_as_uint(b1)));
}

// stage one 32-float row (tf32-rounded) into permuted layout: reg transpose + 8 STS.128
__device__ __forceinline__ void stage_row_perm(float* __restrict__ dstrow,
                                               const float4* __restrict__ src) {
    float4 f[8];
#pragma unroll
    for (int q = 0; q < 8; ++q) {
        float4 v = src[q];
        f[q] = make_float4(to_tf32f(v.x), to_tf32f(v.y), to_tf32f(v.z), to_tf32f(v.w));
    }
    float4* d4 = reinterpret_cast<float4*>(dstrow);
    d4[0] = make_float4(f[0].x, f[1].x, f[2].x, f[3].x);
    d4[1] = make_float4(f[4].x, f[5].x, f[6].x, f[7].x);
    d4[2] = make_float4(f[0].y, f[1].y, f[2].y, f[3].y);
    d4[3] = make_float4(f[4].y, f[5].y, f[6].y, f[7].y);
    d4[4] = make_float4(f[0].z, f[1].z, f[2].z, f[3].z);
    d4[5] = make_float4(f[4].z, f[5].z, f[6].z, f[7].z);
    d4[6] = make_float4(f[0].w, f[1].w, f[2].w, f[3].w);
    d4[7] = make_float4(f[4].w, f[5].w, f[6].w, f[7].w);
}

// C[2][4][4] += A(rows rowbase..+31, permuted) @ W^T (permuted); all LDS.128
__device__ __forceinline__ void gemm32p(const float* __restrict__ sA, int rowbase,
                                        const float* __restrict__ sW,
                                        float C[2][4][4], int g, int tig) {
    float B[4][8];
#pragma unroll
    for (int nt = 0; nt < 4; ++nt) {
        const float4* wr = reinterpret_cast<const float4*>(sW + (nt*8+g)*ST + tig*8);
        float4 w0 = wr[0], w1 = wr[1];
        B[nt][0]=w0.x; B[nt][1]=w0.y; B[nt][2]=w0.z; B[nt][3]=w0.w;
        B[nt][4]=w1.x; B[nt][5]=w1.y; B[nt][6]=w1.z; B[nt][7]=w1.w;
    }
#pragma unroll
    for (int t = 0; t < 2; ++t) {
        int rb = rowbase + 16*t;
        const float4* al = reinterpret_cast<const float4*>(sA + (rb+g)*ST + tig*8);
        const float4* ah = reinterpret_cast<const float4*>(sA + (rb+g+8)*ST + tig*8);
        float4 l0 = al[0], l1 = al[1], h0 = ah[0], h1 = ah[1];
        float lo[8] = {l0.x,l0.y,l0.z,l0.w,l1.x,l1.y,l1.z,l1.w};
        float hi[8] = {h0.x,h0.y,h0.z,h0.w,h1.x,h1.y,h1.z,h1.w};
#pragma unroll
        for (int ks = 0; ks < 4; ++ks)
#pragma unroll
            for (int nt = 0; nt < 4; ++nt)
                mma8(C[t][nt], lo[2*ks], hi[2*ks], lo[2*ks+1], hi[2*ks+1],
                     B[nt][2*ks], B[nt][2*ks+1]);
    }
}

// ---------------- Kernel A: net0 precompute ----------------
__global__ __launch_bounds__(PTPB) void ltcn_precompute(
    const float* __restrict__ u_t, const float* __restrict__ W_in,
    const float* __restrict__ b_in)
{
    __shared__ __align__(16) float sWin[KD*INDIM];
    __shared__ float sbin[KD];
    int tid = threadIdx.x;
    for (int i = tid; i < KD*INDIM; i += PTPB) sWin[i] = W_in[i];
    if (tid < KD) sbin[tid] = b_in[tid];
    __syncthreads();

    int b = blockIdx.x * PTPB + tid;
    if (b >= BATCH) return;

    float u[INDIM];
    const float4* up = reinterpret_cast<const float4*>(u_t + (size_t)b * INDIM);
#pragma unroll
    for (int i = 0; i < INDIM/4; ++i) {
        float4 t = up[i];
        u[4*i+0]=t.x; u[4*i+1]=t.y; u[4*i+2]=t.z; u[4*i+3]=t.w;
    }
    float n0[KD];
#pragma unroll 4
    for (int l = 0; l < KD; ++l) {
        float acc = sbin[l];
        const float4* wr = reinterpret_cast<const float4*>(sWin + l*INDIM);
#pragma unroll
        for (int i = 0; i < INDIM/4; ++i) {
            float4 w = wr[i];
            acc = fmaf(w.x, u[4*i+0], acc);
            acc = fmaf(w.y, u[4*i+1], acc);
            acc = fmaf(w.z, u[4*i+2], acc);
            acc = fmaf(w.w, u[4*i+3], acc);
        }
        n0[l] = fast_tanh(acc);
    }
    float4* op = reinterpret_cast<float4*>(g_net0 + (size_t)b * KD);
#pragma unroll
    for (int i = 0; i < 8; ++i)
        op[i] = make_float4(n0[4*i], n0[4*i+1], n0[4*i+2], n0[4*i+3]);
}

// ---------------- Step kernel ----------------
__global__ __launch_bounds__(TPB, 3) void ltcn_step_mma(
    const float* __restrict__ src, float* __restrict__ dst,
    const float* __restrict__ W_fwd, const float* __restrict__ b_fwd,
    const float* __restrict__ W_rec, const float* __restrict__ b_rec,
    const float* __restrict__ E_l,   const float* __restrict__ E_lr,
    const float* __restrict__ tau_raw, const int* __restrict__ n_steps, int s)
{
    extern __shared__ __align__(16) float smf[];
    const int tid  = threadIdx.x;
    const int wid  = tid >> 5;
    const int lane = tid & 31;
    const int g    = lane >> 2;
    const int tig  = lane & 3;
    const int j    = blockIdx.y;
    const int gRow = blockIdx.x * MTILE;

    const float* ysl = src + (size_t)gRow*NSTATE + (size_t)j*KD;
    float*       odl = dst + (size_t)gRow*NSTATE + (size_t)j*KD;

    if (s >= *n_steps) {   // passthrough
        const float4* in4 = reinterpret_cast<const float4*>(ysl + (size_t)tid*NSTATE);
        float4*       o4  = reinterpret_cast<float4*>(odl + (size_t)tid*NSTATE);
#pragma unroll
        for (int i = 0; i < 8; ++i) o4[i] = in4[i];
        return;
    }

    // ---- stage weights: thread = (mat, row), permuted rows ----
    {
        const int mat = tid >> 5, row = lane;
        const float* wsrc = nullptr;
        float* wdst = nullptr;
        if (mat == 0) { if (j > 0) { wsrc = W_fwd + (size_t)(j-1)*KD*KD + row*KD; wdst = smf + SWF + row*ST; } }
        else if (mat == 1) { wsrc = W_rec + (size_t)j*KD*KD + row*KD; wdst = smf + SWR + row*ST; }
        else if (mat == 2) { wsrc = E_l  + (size_t)j*KD*KD + row*KD; wdst = smf + SEL + row*ST; }
        else               { wsrc = E_lr + (size_t)j*KD*KD + row*KD; wdst = smf + SELR + row*ST; }
        if (wsrc) stage_row_perm(wdst, reinterpret_cast<const float4*>(wsrc));
    }
    // ---- stage activations: thread = row (warp-local rows) ----
    stage_row_perm(smf + SBUFB + tid*ST,
                   reinterpret_cast<const float4*>(ysl + (size_t)tid*NSTATE));
    if (j > 0) {
        stage_row_perm(smf + SBUFA + tid*ST,
                       reinterpret_cast<const float4*>(
                           src + (size_t)(gRow+tid)*NSTATE + (size_t)(j-1)*KD));
    } else {
        stage_row_perm(smf + SBUFA + tid*ST,
                       reinterpret_cast<const float4*>(g_net0 + (size_t)(gRow+tid)*KD));
    }
    if (tid < KD) {
        smf[SBR + tid] = b_rec[j*KD + tid];
        if (j > 0) smf[SBF + tid] = b_fwd[(j-1)*KD + tid];
        float t  = tau_raw[j*KD + tid];
        float sp = (t > 20.f) ? t : log1pf(expf(t));
        smf[SSIT + tid] = 1.0f / (sp + TAU_EPS);
    }
    __syncthreads();

    const int rowbase = wid * 32;
    float aabs[2][4][4], rabs[2][4][4];

    // ---- GEMM P (j>0): bufA(y_{j-1}) @ Wf^T -> actA back into bufA ----
    if (j > 0) {
        float C[2][4][4];
#pragma unroll
        for (int t=0;t<2;++t)
#pragma unroll
            for (int nt=0;nt<4;++nt)
#pragma unroll
                for (int q=0;q<4;++q) C[t][nt][q] = 0.f;
        gemm32p(smf + SBUFA, rowbase, smf + SWF, C, g, tig);
        __syncwarp();   // all sibling reads of bufA done before overwrite
#pragma unroll
        for (int t=0;t<2;++t)
#pragma unroll
            for (int nt=0;nt<4;++nt) {
                int col = nt*8 + 2*tig;
                float b0 = smf[SBF+col], b1 = smf[SBF+col+1];
#pragma unroll
                for (int h=0;h<2;++h) {
                    int r = rowbase + 16*t + g + 8*h;
                    float a0 = fast_tanh(C[t][nt][2*h+0] + b0);
                    float a1 = fast_tanh(C[t][nt][2*h+1] + b1);
                    aabs[t][nt][2*h+0] = fabsf(a0);
                    aabs[t][nt][2*h+1] = fabsf(a1);
                    smf[SBUFA + r*ST + PERM(col)]   = to_tf32f(a0);
                    smf[SBUFA + r*ST + PERM(col+1)] = to_tf32f(a1);
                }
            }
    } else {
        // bufA already holds net0 (permuted); |net0| from gmem in C layout
#pragma unroll
        for (int t=0;t<2;++t)
#pragma unroll
            for (int nt=0;nt<4;++nt) {
                int col = nt*8 + 2*tig;
#pragma unroll
                for (int h=0;h<2;++h) {
                    int r = rowbase + 16*t + g + 8*h;
                    float2 v = *reinterpret_cast<const float2*>(
                        g_net0 + (size_t)(gRow + r)*KD + col);
                    aabs[t][nt][2*h+0] = fabsf(v.x);
                    aabs[t][nt][2*h+1] = fabsf(v.y);
                }
            }
    }

    // ---- GEMM R: bufB(y_j) @ Wr^T -> actR back into bufB ----
    {
        float C[2][4][4];
#pragma unroll
        for (int t=0;t<2;++t)
#pragma unroll
            for (int nt=0;nt<4;++nt)
#pragma unroll
                for (int q=0;q<4;++q) C[t][nt][q] = 0.f;
        gemm32p(smf + SBUFB, rowbase, smf + SWR, C, g, tig);
        __syncwarp();   // reads of bufB done before overwrite
#pragma unroll
        for (int t=0;t<2;++t)
#pragma unroll
            for (int nt=0;nt<4;++nt) {
                int col = nt*8 + 2*tig;
                float b0 = smf[SBR+col], b1 = smf[SBR+col+1];
#pragma unroll
                for (int h=0;h<2;++h) {
                    int r = rowbase + 16*t + g + 8*h;
                    float a0 = fast_tanh(C[t][nt][2*h+0] + b0);
                    float a1 = fast_tanh(C[t][nt][2*h+1] + b1);
                    rabs[t][nt][2*h+0] = fabsf(a0);
                    rabs[t][nt][2*h+1] = fabsf(a1);
                    smf[SBUFB + r*ST + PERM(col)]   = to_tf32f(a0);
                    smf[SBUFB + r*ST + PERM(col+1)] = to_tf32f(a1);
                }
            }
    }
    __syncwarp();   // actA/actR visible to warp before GEMM O

    // ---- GEMM O = actA @ El^T + actR @ Elr^T ----
    float CO[2][4][4];
#pragma unroll
    for (int t=0;t<2;++t)
#pragma unroll
        for (int nt=0;nt<4;++nt)
#pragma unroll
            for (int q=0;q<4;++q) CO[t][nt][q] = 0.f;
    gemm32p(smf + SBUFA, rowbase, smf + SEL,  CO, g, tig);
    gemm32p(smf + SBUFB, rowbase, smf + SELR, CO, g, tig);

    // ---- integrate + store (y reloaded fp32 from gmem) ----
#pragma unroll
    for (int t=0;t<2;++t)
#pragma unroll
        for (int nt=0;nt<4;++nt) {
            int col = nt*8 + 2*tig;
            float s0 = smf[SSIT+col], s1 = smf[SSIT+col+1];
#pragma unroll
            for (int h=0;h<2;++h) {
                int r = rowbase + 16*t + g + 8*h;
                float2 yv = *reinterpret_cast<const float2*>(
                    ysl + (size_t)r*NSTATE + col);
                float d0 = s0 + aabs[t][nt][2*h+0] + rabs[t][nt][2*h+0];
                float d1 = s1 + aabs[t][nt][2*h+1] + rabs[t][nt][2*h+1];
                float y0 = fmaf(DT_C, CO[t][nt][2*h+0] - yv.x*d0, yv.x);
                float y1 = fmaf(DT_C, CO[t][nt][2*h+1] - yv.y*d1, yv.y);
                *reinterpret_cast<float2*>(odl + (size_t)r*NSTATE + col) =
                    make_float2(y0, y1);
            }
        }
}

extern "C" void kernel_launch(void* const* d_in, const int* in_sizes, int n_in,
                              void* d_out, int out_size)
{
    const float* y     = (const float*)d_in[0];
    const float* u_t   = (const float*)d_in[1];
    const float* W_in  = (const float*)d_in[2];
    const float* b_in  = (const float*)d_in[3];
    const float* W_fwd = (const float*)d_in[4];
    const float* b_fwd = (const float*)d_in[5];
    const float* W_rec = (const float*)d_in[6];
    const float* b_rec = (const float*)d_in[7];
    const float* E_l   = (const float*)d_in[8];
    const float* E_lr  = (const float*)d_in[9];
    const float* tau   = (const float*)d_in[10];
    const int*   nst   = (const int*)d_in[11];
    float* out = (float*)d_out;

    float *buf0, *buf1;
    cudaGetSymbolAddress((void**)&buf0, g_buf0);
    cudaGetSymbolAddress((void**)&buf1, g_buf1);

    cudaFuncSetAttribute(ltcn_step_mma,
                         cudaFuncAttributeMaxDynamicSharedMemorySize, SMEM_BYTES);

    ltcn_precompute<<<BATCH/PTPB, PTPB>>>(u_t, W_in, b_in);

    dim3 grid(BATCH/MTILE, NBLK);
    for (int s = 0; s < 8; ++s) {
        const float* srcp = (s == 0) ? y   : ((s & 1) ? buf0 : buf1);
        float*       dstp = (s == 7) ? out : ((s & 1) ? buf1 : buf0);
        ltcn_step_mma<<<grid, TPB, SMEM_BYTES>>>(srcp, dstp, W_fwd, b_fwd,
                                                 W_rec, b_rec, E_l, E_lr,
                                                 tau, nst, s);
    }
}